// round 5
// baseline (speedup 1.0000x reference)
#include <cuda_runtime.h>
#include <cstdint>

#define N_ATOMS 50000
#define M_NBR   32
#define NE      (N_ATOMS * M_NBR)   // 1,600,000 edges
#define NBR_F   64
#define ATOM_F  128
#define SH_DIM  9
#define INV_SQRT_F 0.08838834764831845f  // 1/sqrt(128)

#define TE      128                  // edges per block
#define RS      132                  // s_rdup row stride in floats (2*64 + pad, 16B aligned)
// dynamic smem layout (float offsets)
#define OFF_W    0                   // w1: 64*64
#define OFF_B1   4096                // b1: 64
#define OFF_W2   4160                // w2[:,0]: 64
#define OFF_R    4224                // rdup: 128 * RS
#define SMEM_FLOATS (OFF_R + TE * RS)
#define SMEM_BYTES  (SMEM_FLOATS * 4)   // 84,480 B

__device__ float g_S[N_ATOMS];
__device__ float g_C[N_ATOMS];

__global__ void zero_kernel() {
    int i = blockIdx.x * blockDim.x + threadIdx.x;
    if (i < N_ATOMS) { g_S[i] = 0.0f; g_C[i] = 0.0f; }
}

// ---- f32x2 helpers (sm_103a packed fp32) ----
__device__ __forceinline__ unsigned long long lds_b64(uint32_t addr) {
    unsigned long long v;
    asm volatile("ld.shared.b64 %0, [%1];" : "=l"(v) : "r"(addr));
    return v;
}
__device__ __forceinline__ void lds_v2b64(uint32_t addr, unsigned long long& a,
                                          unsigned long long& b) {
    asm volatile("ld.shared.v2.b64 {%0, %1}, [%2];" : "=l"(a), "=l"(b) : "r"(addr));
}
__device__ __forceinline__ void fma2(unsigned long long& d, unsigned long long a,
                                     unsigned long long b) {
    asm("fma.rn.f32x2 %0, %1, %2, %0;" : "+l"(d) : "l"(a), "l"(b));
}
__device__ __forceinline__ uint32_t smem_u32(const void* p) {
    uint32_t a;
    asm("{ .reg .u64 t; cvta.to.shared.u64 t, %1; cvt.u32.u64 %0, t; }"
        : "=r"(a) : "l"(p));
    return a;
}

// ---------------------------------------------------------------------------
// Edge kernel: blocked GEMM h = radial @ w1 + b1 (f32x2), then
// scalar = softplus(h) . w2[:,0] + b2[0]; atomic accumulate per atom.
// 256 threads: tx_j = tid%8 (8 j-cols each), tx_e = tid/8 (4 edges each).
// ---------------------------------------------------------------------------
__global__ __launch_bounds__(256) void edge_kernel(
    const float* __restrict__ nbr_fea,
    const int*   __restrict__ nbr_idx,
    const float* __restrict__ w1,
    const float* __restrict__ b1,
    const float* __restrict__ w2,
    const float* __restrict__ b2)
{
    extern __shared__ float smem[];
    float* s_w   = smem + OFF_W;
    float* s_b1  = smem + OFF_B1;
    float* s_w2  = smem + OFF_W2;
    float* s_r   = smem + OFF_R;

    const int tid  = threadIdx.x;
    const int tx_j = tid & 7;
    const int tx_e = tid >> 3;
    const int ebase = blockIdx.x * TE;

    // ---- stage w1 (vec4 copy), b1, w2 col0 ----
    {
        const float4* w4 = (const float4*)w1;
        float4* sw4 = (float4*)s_w;
        #pragma unroll
        for (int i = 0; i < 4; i++) sw4[tid + i * 256] = w4[tid + i * 256];
        if (tid < NBR_F) {
            s_b1[tid] = b1[tid];
            s_w2[tid] = w2[tid * SH_DIM];
        }
    }
    // ---- stage radial, duplicated {r,r} pairs, layout s_r[e][2k(+1)] ----
    {
        #pragma unroll
        for (int it = 0; it < 8; it++) {
            int idx = it * 256 + tid;          // [0, 2048)
            int e   = idx >> 4;
            int k4  = idx & 15;
            float4 v = *(const float4*)(nbr_fea + (size_t)(ebase + e) * NBR_F + k4 * 4);
            float2* d = (float2*)(s_r + e * RS + k4 * 8);
            d[0] = make_float2(v.x, v.x);
            d[1] = make_float2(v.y, v.y);
            d[2] = make_float2(v.z, v.z);
            d[3] = make_float2(v.w, v.w);
        }
    }
    __syncthreads();

    // smem byte addresses
    const uint32_t s_base  = smem_u32(smem);
    const uint32_t aw_base = s_base + (OFF_W + tx_j * 8) * 4;            // advance 256B/k
    const uint32_t ar_base = s_base + (OFF_R + (tx_e * 4) * RS) * 4;     // +8B per k, +RS*4 per edge
    const uint32_t ab1     = s_base + (OFF_B1 + tx_j * 8) * 4;

    // ---- init accumulators with b1 pairs ----
    unsigned long long acc[4][4];
    {
        unsigned long long b01, b23;
        lds_v2b64(ab1, b01, b23);                       // {b1[j0],b1[j0+1]},{b1[j0+2],b1[j0+3]}
        unsigned long long b45, b67;
        lds_v2b64(ab1 + 16, b45, b67);
        #pragma unroll
        for (int i = 0; i < 4; i++) {
            acc[i][0] = b01; acc[i][1] = b23; acc[i][2] = b45; acc[i][3] = b67;
        }
    }

    // ---- main loop: h += r * w1 ----
    #pragma unroll 4
    for (int k = 0; k < NBR_F; k++) {
        unsigned long long w01, w23, w45, w67;
        lds_v2b64(aw_base + k * 256, w01, w23);
        lds_v2b64(aw_base + k * 256 + 16, w45, w67);
        unsigned long long r0 = lds_b64(ar_base + k * 8);
        unsigned long long r1 = lds_b64(ar_base + RS * 4 + k * 8);
        unsigned long long r2 = lds_b64(ar_base + RS * 8 + k * 8);
        unsigned long long r3 = lds_b64(ar_base + RS * 12 + k * 8);

        fma2(acc[0][0], r0, w01); fma2(acc[0][1], r0, w23);
        fma2(acc[0][2], r0, w45); fma2(acc[0][3], r0, w67);
        fma2(acc[1][0], r1, w01); fma2(acc[1][1], r1, w23);
        fma2(acc[1][2], r1, w45); fma2(acc[1][3], r1, w67);
        fma2(acc[2][0], r2, w01); fma2(acc[2][1], r2, w23);
        fma2(acc[2][2], r2, w45); fma2(acc[2][3], r2, w67);
        fma2(acc[3][0], r3, w01); fma2(acc[3][1], r3, w23);
        fma2(acc[3][2], r3, w45); fma2(acc[3][3], r3, w67);
    }

    // ---- epilogue: softplus . w2, reduce over 8 j-lanes, atomics ----
    const float b2v = b2[0];
    float w2v[8];
    #pragma unroll
    for (int p = 0; p < 8; p++) w2v[p] = s_w2[tx_j * 8 + p];

    #pragma unroll
    for (int i = 0; i < 4; i++) {
        float s = 0.0f;
        #pragma unroll
        for (int p = 0; p < 4; p++) {
            float lo = __uint_as_float((uint32_t)(acc[i][p] & 0xffffffffULL));
            float hi = __uint_as_float((uint32_t)(acc[i][p] >> 32));
            float sl = fmaxf(lo, 0.0f) + __logf(1.0f + __expf(-fabsf(lo)));
            float sh = fmaxf(hi, 0.0f) + __logf(1.0f + __expf(-fabsf(hi)));
            s = fmaf(sl, w2v[2 * p], s);
            s = fmaf(sh, w2v[2 * p + 1], s);
        }
        // butterfly reduce within 8-lane j-groups
        s += __shfl_xor_sync(0xffffffffu, s, 1);
        s += __shfl_xor_sync(0xffffffffu, s, 2);
        s += __shfl_xor_sync(0xffffffffu, s, 4);
        if (tx_j == 0) {
            int e = ebase + tx_e * 4 + i;
            int a = nbr_idx[e];
            a = (a < 0) ? 0 : (a >= N_ATOMS ? N_ATOMS - 1 : a);
            atomicAdd(&g_S[a], s + b2v);
            atomicAdd(&g_C[a], 1.0f);
        }
    }
}

// ---------------------------------------------------------------------------
// Output GEMM: out[i,:] = (atom_fea[i,:] @ tp_w) * g_S[i]*INV_SQRT_F/max(g_C[i],1)
// ---------------------------------------------------------------------------
__global__ __launch_bounds__(256) void out_kernel(
    const float* __restrict__ atom_fea,
    const float* __restrict__ tp_w,
    float* __restrict__ out)
{
    __shared__ float s_tw[32 * ATOM_F];
    __shared__ float s_af[32 * 32];

    int tid  = threadIdx.x;
    int base = blockIdx.x * 32;
    int j    = tid & 127;
    int ag   = tid >> 7;

    float acc[16];
    #pragma unroll
    for (int a = 0; a < 16; a++) acc[a] = 0.0f;

    for (int kt = 0; kt < ATOM_F / 32; kt++) {
        __syncthreads();
        for (int i = tid; i < 32 * ATOM_F; i += 256)
            s_tw[i] = tp_w[(size_t)(kt * 32) * ATOM_F + i];
        for (int i = tid; i < 32 * 32; i += 256) {
            int a = i >> 5, kk = i & 31;
            int atom = base + a;
            s_af[i] = (atom < N_ATOMS)
                        ? atom_fea[(size_t)atom * ATOM_F + kt * 32 + kk]
                        : 0.0f;
        }
        __syncthreads();

        #pragma unroll
        for (int kk = 0; kk < 32; kk++) {
            float tw = s_tw[kk * ATOM_F + j];
            #pragma unroll
            for (int a = 0; a < 16; a++)
                acc[a] = fmaf(s_af[(ag * 16 + a) * 32 + kk], tw, acc[a]);
        }
    }

    #pragma unroll
    for (int a = 0; a < 16; a++) {
        int atom = base + ag * 16 + a;
        if (atom < N_ATOMS) {
            float c = g_C[atom];
            float scale = g_S[atom] * INV_SQRT_F / fmaxf(c, 1.0f);
            out[(size_t)atom * ATOM_F + j] = acc[a] * scale;
        }
    }
}

// ---------------------------------------------------------------------------
// Launch
// ---------------------------------------------------------------------------
extern "C" void kernel_launch(void* const* d_in, const int* in_sizes, int n_in,
                              void* d_out, int out_size)
{
    const float* atom_fea = (const float*)d_in[0];
    const float* nbr_fea  = (const float*)d_in[1];
    const int*   nbr_idx  = (const int*)d_in[2];
    const float* w1       = (const float*)d_in[3];
    const float* b1       = (const float*)d_in[4];
    const float* w2       = (const float*)d_in[5];
    const float* b2       = (const float*)d_in[6];
    const float* tp_w     = (const float*)d_in[7];
    float*       out      = (float*)d_out;

    cudaFuncSetAttribute(edge_kernel,
                         cudaFuncAttributeMaxDynamicSharedMemorySize, SMEM_BYTES);

    zero_kernel<<<(N_ATOMS + 255) / 256, 256>>>();
    edge_kernel<<<NE / TE, 256, SMEM_BYTES>>>(nbr_fea, nbr_idx, w1, b1, w2, b2);
    out_kernel<<<(N_ATOMS + 31) / 32, 256>>>(atom_fea, tp_w, out);
}

// round 6
// speedup vs baseline: 1.3387x; 1.3387x over previous
#include <cuda_runtime.h>
#include <cstdint>

#define N_ATOMS 50000
#define M_NBR   32
#define NE      (N_ATOMS * M_NBR)   // 1,600,000 edges
#define NBR_F   64
#define ATOM_F  128
#define SH_DIM  9
#define INV_SQRT_F 0.08838834764831845f  // 1/sqrt(128)

#define TE      256                  // edges per block (one per thread)
#define RSTR    68                   // radial row stride in floats (64 + 4 pad)
// dynamic smem layout (float offsets)
#define OFF_W    0                   // w1: 64*64
#define OFF_B1   4096                // b1: 64
#define OFF_W2   4160                // w2[:,0]: 64
#define OFF_R    4224                // radial: TE * RSTR  (16B aligned)
#define SMEM_FLOATS (OFF_R + TE * RSTR)
#define SMEM_BYTES  (SMEM_FLOATS * 4)   // 86,528 B

__device__ float g_S[N_ATOMS];
__device__ float g_C[N_ATOMS];

__global__ void zero_kernel() {
    int i = blockIdx.x * blockDim.x + threadIdx.x;
    if (i < N_ATOMS) { g_S[i] = 0.0f; g_C[i] = 0.0f; }
}

// ---- f32x2 helpers ----
__device__ __forceinline__ unsigned long long lds_b64(uint32_t addr) {
    unsigned long long v;
    asm volatile("ld.shared.b64 %0, [%1];" : "=l"(v) : "r"(addr));
    return v;
}
__device__ __forceinline__ void lds_v2b64(uint32_t addr, unsigned long long& a,
                                          unsigned long long& b) {
    asm volatile("ld.shared.v2.b64 {%0, %1}, [%2];" : "=l"(a), "=l"(b) : "r"(addr));
}
__device__ __forceinline__ void fma2(unsigned long long& d, unsigned long long a,
                                     unsigned long long b) {
    asm("fma.rn.f32x2 %0, %1, %2, %0;" : "+l"(d) : "l"(a), "l"(b));
}
__device__ __forceinline__ unsigned long long splat2(float x) {
    unsigned long long v;
    asm("mov.b64 %0, {%1, %2};" : "=l"(v) : "f"(x), "f"(x));
    return v;
}
__device__ __forceinline__ uint32_t smem_u32(const void* p) {
    uint32_t a;
    asm("{ .reg .u64 t; cvta.to.shared.u64 t, %1; cvt.u32.u64 %0, t; }"
        : "=r"(a) : "l"(p));
    return a;
}

// ---------------------------------------------------------------------------
// Edge kernel: one edge per thread, f32x2 accumulators, w1 rows read as
// full-warp BROADCAST v2.b64 from smem (conflict-free, 1 phase).
// ---------------------------------------------------------------------------
__global__ __launch_bounds__(256, 2) void edge_kernel(
    const float* __restrict__ nbr_fea,
    const int*   __restrict__ nbr_idx,
    const float* __restrict__ w1,
    const float* __restrict__ b1,
    const float* __restrict__ w2,
    const float* __restrict__ b2)
{
    extern __shared__ float smem[];
    float* s_w  = smem + OFF_W;
    float* s_r  = smem + OFF_R;

    const int tid   = threadIdx.x;
    const int ebase = blockIdx.x * TE;

    // ---- stage w1 (vec4), b1, w2[:,0] ----
    {
        const float4* w4 = (const float4*)w1;
        float4* sw4 = (float4*)s_w;
        #pragma unroll
        for (int i = 0; i < 4; i++) sw4[tid + i * 256] = w4[tid + i * 256];
        if (tid < NBR_F) {
            smem[OFF_B1 + tid] = b1[tid];
            smem[OFF_W2 + tid] = w2[tid * SH_DIM];
        }
    }
    // ---- stage radial: coalesced float4 loads, stride-68 rows in smem ----
    {
        #pragma unroll
        for (int it = 0; it < 16; it++) {
            int idx = it * 256 + tid;          // [0, 4096) quads
            int e   = idx >> 4;
            int q   = idx & 15;
            float4 v = *(const float4*)(nbr_fea + (size_t)(ebase + e) * NBR_F + q * 4);
            *(float4*)(s_r + e * RSTR + q * 4) = v;
        }
    }
    __syncthreads();

    const uint32_t s_base = smem_u32(smem);
    const uint32_t aw     = s_base + OFF_W * 4;                 // uniform (broadcast)
    const uint32_t ab1    = s_base + OFF_B1 * 4;                // uniform
    const float4*  my_r   = (const float4*)(s_r + tid * RSTR);

    // ---- init 32 f32x2 accumulators with b1 (broadcast loads) ----
    unsigned long long acc[32];
    #pragma unroll
    for (int t = 0; t < 16; t++)
        lds_v2b64(ab1 + t * 16, acc[2 * t], acc[2 * t + 1]);

    // ---- main loop: h += r_k * w1[k,:]  (w broadcast, r splat) ----
    #pragma unroll 2
    for (int kq = 0; kq < 16; kq++) {
        float4 rv = my_r[kq];
        float rr[4] = {rv.x, rv.y, rv.z, rv.w};
        #pragma unroll
        for (int s = 0; s < 4; s++) {
            const int k = kq * 4 + s;
            unsigned long long rp = splat2(rr[s]);
            const uint32_t awk = aw + k * 256;      // 64 floats per row
            #pragma unroll
            for (int t = 0; t < 16; t++) {
                unsigned long long wA, wB;
                lds_v2b64(awk + t * 16, wA, wB);    // broadcast
                fma2(acc[2 * t],     rp, wA);
                fma2(acc[2 * t + 1], rp, wB);
            }
        }
    }

    // ---- epilogue: softplus . w2[:,0] + b2[0], one atomic per edge ----
    float s = b2[0];
    const uint32_t aw2 = s_base + OFF_W2 * 4;
    #pragma unroll
    for (int p = 0; p < 32; p++) {
        unsigned long long w2p = lds_b64(aw2 + p * 8);   // broadcast
        float w2lo = __uint_as_float((uint32_t)(w2p & 0xffffffffULL));
        float w2hi = __uint_as_float((uint32_t)(w2p >> 32));
        float lo = __uint_as_float((uint32_t)(acc[p] & 0xffffffffULL));
        float hi = __uint_as_float((uint32_t)(acc[p] >> 32));
        float sl = fmaxf(lo, 0.0f) + __logf(1.0f + __expf(-fabsf(lo)));
        float sh = fmaxf(hi, 0.0f) + __logf(1.0f + __expf(-fabsf(hi)));
        s = fmaf(sl, w2lo, s);
        s = fmaf(sh, w2hi, s);
    }

    int a = nbr_idx[ebase + tid];
    a = (a < 0) ? 0 : (a >= N_ATOMS ? N_ATOMS - 1 : a);
    atomicAdd(&g_S[a], s);
    atomicAdd(&g_C[a], 1.0f);
}

// ---------------------------------------------------------------------------
// Output GEMM (f32x2): out[i,:] = (atom_fea[i,:] @ tp_w) * scale(i)
// 32 atoms x 128 cols per block; thread owns col pair (2*tx_j, 2*tx_j+1)
// for 8 atoms. tp_w pairs natural-contiguous; atom values splat-duplicated.
// ---------------------------------------------------------------------------
__global__ __launch_bounds__(256) void out_kernel(
    const float* __restrict__ atom_fea,
    const float* __restrict__ tp_w,
    float* __restrict__ out)
{
    __shared__ float s_tw[32 * ATOM_F];                 // 16 KB
    __shared__ unsigned long long s_afd[32 * 32];       // 8 KB, {v,v} pairs

    const int tid  = threadIdx.x;
    const int base = blockIdx.x * 32;
    const int tx_j = tid & 63;      // column pair index
    const int ag   = tid >> 6;      // atom group (8 atoms each)

    const uint32_t atw = smem_u32(s_tw);
    const uint32_t aaf = smem_u32(s_afd);

    unsigned long long acc[8];
    #pragma unroll
    for (int a = 0; a < 8; a++) acc[a] = 0ULL;

    for (int kt = 0; kt < ATOM_F / 32; kt++) {
        __syncthreads();
        for (int i = tid; i < 32 * ATOM_F; i += 256)
            s_tw[i] = tp_w[(size_t)(kt * 32) * ATOM_F + i];
        for (int i = tid; i < 32 * 32; i += 256) {
            int a = i >> 5, kk = i & 31;
            int atom = base + a;
            float v = (atom < N_ATOMS)
                        ? atom_fea[(size_t)atom * ATOM_F + kt * 32 + kk]
                        : 0.0f;
            s_afd[i] = splat2(v);
        }
        __syncthreads();

        #pragma unroll 8
        for (int kk = 0; kk < 32; kk++) {
            unsigned long long w = lds_b64(atw + (kk * ATOM_F + 2 * tx_j) * 4);
            #pragma unroll
            for (int a = 0; a < 8; a++) {
                unsigned long long af = lds_b64(aaf + ((ag * 8 + a) * 32 + kk) * 8); // broadcast
                fma2(acc[a], af, w);
            }
        }
    }

    #pragma unroll
    for (int a = 0; a < 8; a++) {
        int atom = base + ag * 8 + a;
        if (atom < N_ATOMS) {
            float c = g_C[atom];
            float scale = g_S[atom] * INV_SQRT_F / fmaxf(c, 1.0f);
            float lo = __uint_as_float((uint32_t)(acc[a] & 0xffffffffULL));
            float hi = __uint_as_float((uint32_t)(acc[a] >> 32));
            *(float2*)(out + (size_t)atom * ATOM_F + 2 * tx_j) =
                make_float2(lo * scale, hi * scale);
        }
    }
}

// ---------------------------------------------------------------------------
// Launch
// ---------------------------------------------------------------------------
extern "C" void kernel_launch(void* const* d_in, const int* in_sizes, int n_in,
                              void* d_out, int out_size)
{
    const float* atom_fea = (const float*)d_in[0];
    const float* nbr_fea  = (const float*)d_in[1];
    const int*   nbr_idx  = (const int*)d_in[2];
    const float* w1       = (const float*)d_in[3];
    const float* b1       = (const float*)d_in[4];
    const float* w2       = (const float*)d_in[5];
    const float* b2       = (const float*)d_in[6];
    const float* tp_w     = (const float*)d_in[7];
    float*       out      = (float*)d_out;

    cudaFuncSetAttribute(edge_kernel,
                         cudaFuncAttributeMaxDynamicSharedMemorySize, SMEM_BYTES);

    zero_kernel<<<(N_ATOMS + 255) / 256, 256>>>();
    edge_kernel<<<NE / TE, 256, SMEM_BYTES>>>(nbr_fea, nbr_idx, w1, b1, w2, b2);
    out_kernel<<<(N_ATOMS + 31) / 32, 256>>>(atom_fea, tp_w, out);
}

// round 8
// speedup vs baseline: 1.8406x; 1.3750x over previous
#include <cuda_runtime.h>
#include <cuda_bf16.h>
#include <cstdint>

#define N_ATOMS 50000
#define M_NBR   32
#define NE      (N_ATOMS * M_NBR)   // 1,600,000 edges
#define NBR_F   64
#define ATOM_F  128
#define SH_DIM  9
#define INV_SQRT_F 0.08838834764831845f

#define TILE_E  256                  // edges per CTA (8 warps x 32 edges)
#define N_TILES (NE / TILE_E)        // 6250

// ---- edge-kernel smem layout (byte offsets from 1024-aligned base) ----
#define OFF_A_HI   0                 // 256 x 64 bf16, swizzled 128B rows (32768)
#define OFF_A_LO   32768             // 32768
#define OFF_B_HI   65536             // 64 x 64 bf16 row-major [k][j], swz (8192)
#define OFF_B_LO   73728             // 8192
#define OFF_B1     81920             // 64 f32
#define OFF_W2     82176             // 64 f32
#define EDGE_SMEM_USED 82432
#define EDGE_SMEM_BYTES (EDGE_SMEM_USED + 1024)

__device__ float g_S[N_ATOMS];
__device__ float g_C[N_ATOMS];

__global__ void zero_kernel() {
    int i = blockIdx.x * blockDim.x + threadIdx.x;
    if (i < N_ATOMS) { g_S[i] = 0.0f; g_C[i] = 0.0f; }
}

// ======================= helpers =======================
__device__ __forceinline__ uint32_t smem_u32(const void* p) {
    uint32_t a;
    asm("{ .reg .u64 t; cvta.to.shared.u64 t, %1; cvt.u32.u64 %0, t; }"
        : "=r"(a) : "l"(p));
    return a;
}
__device__ __forceinline__ void sts64(uint32_t addr, unsigned long long v) {
    asm volatile("st.shared.b64 [%0], %1;" :: "r"(addr), "l"(v) : "memory");
}
__device__ __forceinline__ void sts16(uint32_t addr, unsigned short v) {
    asm volatile("st.shared.b16 [%0], %1;" :: "r"(addr), "h"(v) : "memory");
}
#define SMEM_SWZ(off) ((off) ^ (((off) >> 3) & 0x70))

__device__ __forceinline__ void ldsm_x4(uint32_t addr, uint32_t* r) {
    asm volatile("ldmatrix.sync.aligned.m8n8.x4.shared.b16 {%0,%1,%2,%3}, [%4];"
        : "=r"(r[0]), "=r"(r[1]), "=r"(r[2]), "=r"(r[3]) : "r"(addr));
}
__device__ __forceinline__ void ldsm_x2t(uint32_t addr, uint32_t& a, uint32_t& b) {
    asm volatile("ldmatrix.sync.aligned.m8n8.x2.trans.shared.b16 {%0,%1}, [%2];"
        : "=r"(a), "=r"(b) : "r"(addr));
}
__device__ __forceinline__ void mma_bf16(float* d, const uint32_t* a,
                                         uint32_t b0, uint32_t b1) {
    asm volatile("mma.sync.aligned.m16n8k16.row.col.f32.bf16.bf16.f32 "
        "{%0,%1,%2,%3}, {%4,%5,%6,%7}, {%8,%9}, {%0,%1,%2,%3};"
        : "+f"(d[0]), "+f"(d[1]), "+f"(d[2]), "+f"(d[3])
        : "r"(a[0]), "r"(a[1]), "r"(a[2]), "r"(a[3]), "r"(b0), "r"(b1));
}
__device__ __forceinline__ unsigned short bf_bits(__nv_bfloat16 b) {
    return *reinterpret_cast<unsigned short*>(&b);
}

// ---------------------------------------------------------------------------
// Edge kernel: per 256-edge tile, h = radial @ w1 on HMMA (mma.sync bf16,
// 3-pass hi/lo split, fp32 acc), epilogue softplus . w2[:,0] + atomics.
// Warp w handles edges [w*32, w*32+32) of the tile (two m16 tiles).
// ---------------------------------------------------------------------------
__global__ __launch_bounds__(256) void edge_kernel(
    const float* __restrict__ nbr_fea,
    const int*   __restrict__ nbr_idx,
    const float* __restrict__ w1,
    const float* __restrict__ b1,
    const float* __restrict__ w2,
    const float* __restrict__ b2)
{
    extern __shared__ char dyn[];
    const uint32_t raw  = smem_u32(dyn);
    const uint32_t base = (raw + 1023u) & ~1023u;
    char* bp = dyn + (base - raw);

    const int tid  = threadIdx.x;
    const int wid  = tid >> 5;
    const int lane = tid & 31;
    const int gid  = lane >> 2;     // row group 0-7
    const int tid4 = lane & 3;      // col group 0-3
    const int tb   = blockIdx.x * TILE_E;

    // ---- stage B = w1 row-major [k][j], bf16 hi/lo, swizzled 128B rows ----
    #pragma unroll
    for (int it = 0; it < 16; it++) {
        int idx = it * 256 + tid;          // [0, 4096)
        int k = idx >> 6, j = idx & 63;
        float v = w1[idx];                 // w1[k][j], coalesced
        __nv_bfloat16 bh = __float2bfloat16(v);
        __nv_bfloat16 bl = __float2bfloat16(v - __bfloat162float(bh));
        uint32_t off = SMEM_SWZ((uint32_t)(k * 128 + j * 2));
        sts16(base + OFF_B_HI + off, bf_bits(bh));
        sts16(base + OFF_B_LO + off, bf_bits(bl));
    }
    if (tid < NBR_F) {
        *(float*)(bp + OFF_B1 + tid * 4) = b1[tid];
        *(float*)(bp + OFF_W2 + tid * 4) = w2[tid * SH_DIM];
    }

    // ---- stage A = radial tile (256 x 64) bf16 hi/lo ----
    #pragma unroll
    for (int it = 0; it < 16; it++) {
        int idx = it * 256 + tid;          // [0, 4096) float4 quads
        int row = idx >> 4, q = idx & 15;
        float4 v = *(const float4*)(nbr_fea + (size_t)(tb + row) * NBR_F + q * 4);
        float f[4] = {v.x, v.y, v.z, v.w};
        unsigned long long hi = 0, lo = 0;
        #pragma unroll
        for (int s = 0; s < 4; s++) {
            __nv_bfloat16 bh = __float2bfloat16(f[s]);
            __nv_bfloat16 bl = __float2bfloat16(f[s] - __bfloat162float(bh));
            hi |= (unsigned long long)bf_bits(bh) << (16 * s);
            lo |= (unsigned long long)bf_bits(bl) << (16 * s);
        }
        uint32_t off = SMEM_SWZ((uint32_t)(row * 128 + q * 8));
        sts64(base + OFF_A_HI + off, hi);
        sts64(base + OFF_A_LO + off, lo);
    }
    __syncthreads();

    // ---- mainloop: 3 passes x 4 k-steps, 2 m-tiles x 8 n-tiles ----
    float acc[2][8][4];
    #pragma unroll
    for (int mt = 0; mt < 2; mt++)
        #pragma unroll
        for (int nt = 0; nt < 8; nt++)
            #pragma unroll
            for (int c = 0; c < 4; c++) acc[mt][nt][c] = 0.0f;

    #pragma unroll
    for (int pass = 0; pass < 3; pass++) {
        const uint32_t ab = base + (pass == 1 ? OFF_A_LO : OFF_A_HI);
        const uint32_t bb = base + (pass == 2 ? OFF_B_LO : OFF_B_HI);
        #pragma unroll
        for (int ks = 0; ks < 4; ks++) {
            uint32_t af[2][4];
            #pragma unroll
            for (int mt = 0; mt < 2; mt++) {
                uint32_t off = (uint32_t)((wid * 32 + mt * 16 + (lane & 15)) * 128
                                          + ks * 32 + (lane >> 4) * 16);
                ldsm_x4(ab + SMEM_SWZ(off), af[mt]);
            }
            #pragma unroll
            for (int nt = 0; nt < 8; nt++) {
                uint32_t boff = (uint32_t)((ks * 16 + (lane & 15)) * 128 + nt * 16);
                uint32_t b0, b1r;
                ldsm_x2t(bb + SMEM_SWZ(boff), b0, b1r);
                mma_bf16(acc[0][nt], af[0], b0, b1r);
                mma_bf16(acc[1][nt], af[1], b0, b1r);
            }
        }
    }

    // ---- epilogue: softplus . w2, quad-reduce, atomics ----
    const float b2v = b2[0];
    #pragma unroll
    for (int mt = 0; mt < 2; mt++) {
        #pragma unroll
        for (int rh = 0; rh < 2; rh++) {
            float s = 0.0f;
            #pragma unroll
            for (int nt = 0; nt < 8; nt++) {
                int col = nt * 8 + tid4 * 2;
                float2 b1p = *(const float2*)(bp + OFF_B1 + col * 4);
                float2 w2p = *(const float2*)(bp + OFF_W2 + col * 4);
                float h0 = acc[mt][nt][rh * 2]     + b1p.x;
                float h1 = acc[mt][nt][rh * 2 + 1] + b1p.y;
                float s0 = fmaxf(h0, 0.0f) + __logf(1.0f + __expf(-fabsf(h0)));
                float s1 = fmaxf(h1, 0.0f) + __logf(1.0f + __expf(-fabsf(h1)));
                s = fmaf(s0, w2p.x, s);
                s = fmaf(s1, w2p.y, s);
            }
            s += __shfl_xor_sync(0xffffffffu, s, 1);
            s += __shfl_xor_sync(0xffffffffu, s, 2);
            if (tid4 == 0) {
                int r = wid * 32 + mt * 16 + rh * 8 + gid;
                int a = nbr_idx[tb + r];
                a = (a < 0) ? 0 : (a >= N_ATOMS ? N_ATOMS - 1 : a);
                atomicAdd(&g_S[a], s + b2v);
                atomicAdd(&g_C[a], 1.0f);
            }
        }
    }
}

// ---------------------------------------------------------------------------
// Output GEMM (f32x2), unchanged from R5 (passing).
// ---------------------------------------------------------------------------
__device__ __forceinline__ unsigned long long lds_b64(uint32_t addr) {
    unsigned long long v;
    asm volatile("ld.shared.b64 %0, [%1];" : "=l"(v) : "r"(addr));
    return v;
}
__device__ __forceinline__ void fma2(unsigned long long& d, unsigned long long a,
                                     unsigned long long b) {
    asm("fma.rn.f32x2 %0, %1, %2, %0;" : "+l"(d) : "l"(a), "l"(b));
}
__device__ __forceinline__ unsigned long long splat2(float x) {
    unsigned long long v;
    asm("mov.b64 %0, {%1, %2};" : "=l"(v) : "f"(x), "f"(x));
    return v;
}

__global__ __launch_bounds__(256) void out_kernel(
    const float* __restrict__ atom_fea,
    const float* __restrict__ tp_w,
    float* __restrict__ out)
{
    __shared__ float s_tw[32 * ATOM_F];
    __shared__ unsigned long long s_afd[32 * 32];

    const int tid  = threadIdx.x;
    const int base = blockIdx.x * 32;
    const int tx_j = tid & 63;
    const int ag   = tid >> 6;

    const uint32_t atw = smem_u32(s_tw);
    const uint32_t aaf = smem_u32(s_afd);

    unsigned long long acc[8];
    #pragma unroll
    for (int a = 0; a < 8; a++) acc[a] = 0ULL;

    for (int kt = 0; kt < ATOM_F / 32; kt++) {
        __syncthreads();
        for (int i = tid; i < 32 * ATOM_F; i += 256)
            s_tw[i] = tp_w[(size_t)(kt * 32) * ATOM_F + i];
        for (int i = tid; i < 32 * 32; i += 256) {
            int a = i >> 5, kk = i & 31;
            int atom = base + a;
            float v = (atom < N_ATOMS)
                        ? atom_fea[(size_t)atom * ATOM_F + kt * 32 + kk]
                        : 0.0f;
            s_afd[i] = splat2(v);
        }
        __syncthreads();

        #pragma unroll 8
        for (int kk = 0; kk < 32; kk++) {
            unsigned long long w = lds_b64(atw + (kk * ATOM_F + 2 * tx_j) * 4);
            #pragma unroll
            for (int a = 0; a < 8; a++) {
                unsigned long long af = lds_b64(aaf + ((ag * 8 + a) * 32 + kk) * 8);
                fma2(acc[a], af, w);
            }
        }
    }

    #pragma unroll
    for (int a = 0; a < 8; a++) {
        int atom = base + ag * 8 + a;
        if (atom < N_ATOMS) {
            float c = g_C[atom];
            float scale = g_S[atom] * INV_SQRT_F / fmaxf(c, 1.0f);
            float lo = __uint_as_float((uint32_t)(acc[a] & 0xffffffffULL));
            float hi = __uint_as_float((uint32_t)(acc[a] >> 32));
            *(float2*)(out + (size_t)atom * ATOM_F + 2 * tx_j) =
                make_float2(lo * scale, hi * scale);
        }
    }
}

// ---------------------------------------------------------------------------
// Launch
// ---------------------------------------------------------------------------
extern "C" void kernel_launch(void* const* d_in, const int* in_sizes, int n_in,
                              void* d_out, int out_size)
{
    const float* atom_fea = (const float*)d_in[0];
    const float* nbr_fea  = (const float*)d_in[1];
    const int*   nbr_idx  = (const int*)d_in[2];
    const float* w1       = (const float*)d_in[3];
    const float* b1       = (const float*)d_in[4];
    const float* w2       = (const float*)d_in[5];
    const float* b2       = (const float*)d_in[6];
    const float* tp_w     = (const float*)d_in[7];
    float*       out      = (float*)d_out;

    cudaFuncSetAttribute(edge_kernel,
                         cudaFuncAttributeMaxDynamicSharedMemorySize,
                         EDGE_SMEM_BYTES);

    zero_kernel<<<(N_ATOMS + 255) / 256, 256>>>();
    edge_kernel<<<N_TILES, 256, EDGE_SMEM_BYTES>>>(nbr_fea, nbr_idx, w1, b1, w2, b2);
    out_kernel<<<(N_ATOMS + 31) / 32, 256>>>(atom_fea, tp_w, out);
}

// round 9
// speedup vs baseline: 2.1061x; 1.1442x over previous
#include <cuda_runtime.h>
#include <cuda_bf16.h>
#include <cstdint>

#define N_ATOMS 50000
#define M_NBR   32
#define NE      (N_ATOMS * M_NBR)   // 1,600,000 edges
#define NBR_F   64
#define ATOM_F  128
#define SH_DIM  9
#define INV_SQRT_F 0.08838834764831845f

#define TILE_E        128            // edges per tile (8 warps x 16 edges)
#define TILES_PER_CTA 4
#define N_CTAS (NE / (TILE_E * TILES_PER_CTA))   // 3125

// ---- edge-kernel smem layout (byte offsets from 1024-aligned base) ----
#define OFF_A_HI   0                 // 128 x 64 bf16, swizzled 128B rows (16384)
#define OFF_A_LO   16384             // 16384
#define OFF_B_HI   32768             // 64 x 64 bf16 row-major [k][j], swz (8192)
#define OFF_B_LO   40960             // 8192
#define OFF_B1     49152             // 64 f32
#define OFF_W2     49408             // 64 f32
#define EDGE_SMEM_USED 49664
#define EDGE_SMEM_BYTES (EDGE_SMEM_USED + 1024)

__device__ float g_S[N_ATOMS];
__device__ float g_C[N_ATOMS];

__global__ void zero_kernel() {
    int i = blockIdx.x * blockDim.x + threadIdx.x;
    if (i < N_ATOMS) { g_S[i] = 0.0f; g_C[i] = 0.0f; }
}

// ======================= helpers =======================
__device__ __forceinline__ uint32_t smem_u32(const void* p) {
    uint32_t a;
    asm("{ .reg .u64 t; cvta.to.shared.u64 t, %1; cvt.u32.u64 %0, t; }"
        : "=r"(a) : "l"(p));
    return a;
}
__device__ __forceinline__ void sts64(uint32_t addr, unsigned long long v) {
    asm volatile("st.shared.b64 [%0], %1;" :: "r"(addr), "l"(v) : "memory");
}
__device__ __forceinline__ void sts16(uint32_t addr, unsigned short v) {
    asm volatile("st.shared.b16 [%0], %1;" :: "r"(addr), "h"(v) : "memory");
}
#define SMEM_SWZ(off) ((off) ^ (((off) >> 3) & 0x70))

__device__ __forceinline__ void ldsm_x4(uint32_t addr, uint32_t* r) {
    asm volatile("ldmatrix.sync.aligned.m8n8.x4.shared.b16 {%0,%1,%2,%3}, [%4];"
        : "=r"(r[0]), "=r"(r[1]), "=r"(r[2]), "=r"(r[3]) : "r"(addr));
}
__device__ __forceinline__ void ldsm_x2t(uint32_t addr, uint32_t& a, uint32_t& b) {
    asm volatile("ldmatrix.sync.aligned.m8n8.x2.trans.shared.b16 {%0,%1}, [%2];"
        : "=r"(a), "=r"(b) : "r"(addr));
}
__device__ __forceinline__ void mma_bf16(float* d, const uint32_t* a,
                                         uint32_t b0, uint32_t b1) {
    asm volatile("mma.sync.aligned.m16n8k16.row.col.f32.bf16.bf16.f32 "
        "{%0,%1,%2,%3}, {%4,%5,%6,%7}, {%8,%9}, {%0,%1,%2,%3};"
        : "+f"(d[0]), "+f"(d[1]), "+f"(d[2]), "+f"(d[3])
        : "r"(a[0]), "r"(a[1]), "r"(a[2]), "r"(a[3]), "r"(b0), "r"(b1));
}
__device__ __forceinline__ unsigned short bf_bits(__nv_bfloat16 b) {
    return *reinterpret_cast<unsigned short*>(&b);
}
__device__ __forceinline__ uint32_t cvt_bf2(float hi, float lo) {
    uint32_t r;
    asm("cvt.rn.bf16x2.f32 %0, %1, %2;" : "=r"(r) : "f"(hi), "f"(lo));
    return r;
}
__device__ __forceinline__ unsigned long long pack64(uint32_t lo, uint32_t hi) {
    unsigned long long v;
    asm("mov.b64 %0, {%1, %2};" : "=l"(v) : "r"(lo), "r"(hi));
    return v;
}

// ---------------------------------------------------------------------------
// Edge kernel: per 128-edge tile, h = radial @ w1 on HMMA (3-pass bf16 hi/lo
// split, fp32 acc), epilogue softplus . w2[:,0] + atomics. Warp w owns edges
// [w*16, w*16+16). Each CTA processes TILES_PER_CTA tiles (B staged once).
// ---------------------------------------------------------------------------
__global__ __launch_bounds__(256, 3) void edge_kernel(
    const float* __restrict__ nbr_fea,
    const int*   __restrict__ nbr_idx,
    const float* __restrict__ w1,
    const float* __restrict__ b1,
    const float* __restrict__ w2,
    const float* __restrict__ b2)
{
    extern __shared__ char dyn[];
    const uint32_t raw  = smem_u32(dyn);
    const uint32_t base = (raw + 1023u) & ~1023u;
    char* bp = dyn + (base - raw);

    const int tid  = threadIdx.x;
    const int wid  = tid >> 5;
    const int lane = tid & 31;
    const int gid  = lane >> 2;     // row group 0-7
    const int tid4 = lane & 3;      // col group 0-3

    // ---- stage B = w1 row-major [k][j], bf16 hi/lo, swizzled (once/CTA) ----
    #pragma unroll
    for (int it = 0; it < 16; it++) {
        int idx = it * 256 + tid;          // [0, 4096)
        int k = idx >> 6, j = idx & 63;
        float v = w1[idx];
        __nv_bfloat16 bh = __float2bfloat16(v);
        __nv_bfloat16 bl = __float2bfloat16(v - __bfloat162float(bh));
        uint32_t off = SMEM_SWZ((uint32_t)(k * 128 + j * 2));
        sts16(base + OFF_B_HI + off, bf_bits(bh));
        sts16(base + OFF_B_LO + off, bf_bits(bl));
    }
    if (tid < NBR_F) {
        *(float*)(bp + OFF_B1 + tid * 4) = b1[tid];
        *(float*)(bp + OFF_W2 + tid * 4) = w2[tid * SH_DIM];
    }
    const float b2v = b2[0];

    for (int t = 0; t < TILES_PER_CTA; t++) {
        const int tb = (blockIdx.x * TILES_PER_CTA + t) * TILE_E;

        __syncthreads();   // prev tile's ldsm reads done / B ready (t==0)

        // ---- stage A = radial tile (128 x 64) bf16 hi/lo, packed cvt ----
        #pragma unroll
        for (int it = 0; it < 8; it++) {
            int idx = it * 256 + tid;      // [0, 2048) float4 quads
            int row = idx >> 4, q = idx & 15;
            float4 v = *(const float4*)(nbr_fea + (size_t)(tb + row) * NBR_F + q * 4);
            uint32_t h01 = cvt_bf2(v.y, v.x);
            uint32_t h23 = cvt_bf2(v.w, v.z);
            float f0 = __uint_as_float(h01 << 16);
            float f1 = __uint_as_float(h01 & 0xffff0000u);
            float f2 = __uint_as_float(h23 << 16);
            float f3 = __uint_as_float(h23 & 0xffff0000u);
            uint32_t l01 = cvt_bf2(v.y - f1, v.x - f0);
            uint32_t l23 = cvt_bf2(v.w - f3, v.z - f2);
            uint32_t off = SMEM_SWZ((uint32_t)(row * 128 + q * 8));
            sts64(base + OFF_A_HI + off, pack64(h01, h23));
            sts64(base + OFF_A_LO + off, pack64(l01, l23));
        }
        __syncthreads();

        // ---- mainloop: 3 passes x 4 k-steps x 8 n-tiles ----
        float acc[8][4];
        #pragma unroll
        for (int nt = 0; nt < 8; nt++)
            #pragma unroll
            for (int c = 0; c < 4; c++) acc[nt][c] = 0.0f;

        #pragma unroll
        for (int pass = 0; pass < 3; pass++) {
            const uint32_t ab = base + (pass == 1 ? OFF_A_LO : OFF_A_HI);
            const uint32_t bb = base + (pass == 2 ? OFF_B_LO : OFF_B_HI);
            #pragma unroll
            for (int ks = 0; ks < 4; ks++) {
                uint32_t af[4];
                uint32_t aoff = (uint32_t)((wid * 16 + (lane & 15)) * 128
                                           + ks * 32 + (lane >> 4) * 16);
                ldsm_x4(ab + SMEM_SWZ(aoff), af);
                #pragma unroll
                for (int nt = 0; nt < 8; nt++) {
                    uint32_t boff = (uint32_t)((ks * 16 + (lane & 15)) * 128 + nt * 16);
                    uint32_t b0, b1r;
                    ldsm_x2t(bb + SMEM_SWZ(boff), b0, b1r);
                    mma_bf16(acc[nt], af, b0, b1r);
                }
            }
        }

        // ---- epilogue: softplus . w2, quad-reduce, atomics ----
        float s0 = 0.0f, s1 = 0.0f;
        #pragma unroll
        for (int nt = 0; nt < 8; nt++) {
            int col = nt * 8 + tid4 * 2;
            float2 b1p = *(const float2*)(bp + OFF_B1 + col * 4);
            float2 w2p = *(const float2*)(bp + OFF_W2 + col * 4);
            float h0 = acc[nt][0] + b1p.x;   // row gid
            float h1 = acc[nt][1] + b1p.y;
            float h2 = acc[nt][2] + b1p.x;   // row gid+8
            float h3 = acc[nt][3] + b1p.y;
            float p0 = fmaxf(h0, 0.0f) + __logf(1.0f + __expf(-fabsf(h0)));
            float p1 = fmaxf(h1, 0.0f) + __logf(1.0f + __expf(-fabsf(h1)));
            float p2 = fmaxf(h2, 0.0f) + __logf(1.0f + __expf(-fabsf(h2)));
            float p3 = fmaxf(h3, 0.0f) + __logf(1.0f + __expf(-fabsf(h3)));
            s0 = fmaf(p0, w2p.x, s0); s0 = fmaf(p1, w2p.y, s0);
            s1 = fmaf(p2, w2p.x, s1); s1 = fmaf(p3, w2p.y, s1);
        }
        s0 += __shfl_xor_sync(0xffffffffu, s0, 1);
        s0 += __shfl_xor_sync(0xffffffffu, s0, 2);
        s1 += __shfl_xor_sync(0xffffffffu, s1, 1);
        s1 += __shfl_xor_sync(0xffffffffu, s1, 2);
        if (tid4 == 0) {
            int r0 = wid * 16 + gid;
            int a0 = nbr_idx[tb + r0];
            a0 = (a0 < 0) ? 0 : (a0 >= N_ATOMS ? N_ATOMS - 1 : a0);
            atomicAdd(&g_S[a0], s0 + b2v);
            atomicAdd(&g_C[a0], 1.0f);
            int r1 = r0 + 8;
            int a1 = nbr_idx[tb + r1];
            a1 = (a1 < 0) ? 0 : (a1 >= N_ATOMS ? N_ATOMS - 1 : a1);
            atomicAdd(&g_S[a1], s1 + b2v);
            atomicAdd(&g_C[a1], 1.0f);
        }
    }
}

// ---------------------------------------------------------------------------
// Output GEMM (f32x2): out[i,:] = (atom_fea[i,:] @ tp_w) * scale(i)
// s_afd re-laid out [kk][atom] (stride 34) so 8 atoms come via 4 broadcast
// LDS.128 per kk instead of 8 LDS.64.
// ---------------------------------------------------------------------------
__device__ __forceinline__ unsigned long long lds_b64(uint32_t addr) {
    unsigned long long v;
    asm volatile("ld.shared.b64 %0, [%1];" : "=l"(v) : "r"(addr));
    return v;
}
__device__ __forceinline__ void lds_v2u64(uint32_t addr, unsigned long long& a,
                                          unsigned long long& b) {
    asm volatile("ld.shared.v2.u64 {%0, %1}, [%2];" : "=l"(a), "=l"(b) : "r"(addr));
}
__device__ __forceinline__ void fma2(unsigned long long& d, unsigned long long a,
                                     unsigned long long b) {
    asm("fma.rn.f32x2 %0, %1, %2, %0;" : "+l"(d) : "l"(a), "l"(b));
}
__device__ __forceinline__ unsigned long long splat2(float x) {
    unsigned long long v;
    asm("mov.b64 %0, {%1, %2};" : "=l"(v) : "f"(x), "f"(x));
    return v;
}

#define AFD_STRIDE 34

__global__ __launch_bounds__(256) void out_kernel(
    const float* __restrict__ atom_fea,
    const float* __restrict__ tp_w,
    float* __restrict__ out)
{
    __shared__ float s_tw[32 * ATOM_F];                     // 16 KB
    __shared__ unsigned long long s_afd[32 * AFD_STRIDE];   // 8.5 KB

    const int tid  = threadIdx.x;
    const int base = blockIdx.x * 32;
    const int tx_j = tid & 63;
    const int ag   = tid >> 6;

    const uint32_t atw = smem_u32(s_tw);
    const uint32_t aaf = smem_u32(s_afd);

    unsigned long long acc[8];
    #pragma unroll
    for (int a = 0; a < 8; a++) acc[a] = 0ULL;

    for (int kt = 0; kt < ATOM_F / 32; kt++) {
        __syncthreads();
        for (int i = tid; i < 32 * ATOM_F; i += 256)
            s_tw[i] = tp_w[(size_t)(kt * 32) * ATOM_F + i];
        for (int i = tid; i < 32 * 32; i += 256) {
            int a = i >> 5, kk = i & 31;                    // coalesced load
            int atom = base + a;
            float v = (atom < N_ATOMS)
                        ? atom_fea[(size_t)atom * ATOM_F + kt * 32 + kk]
                        : 0.0f;
            s_afd[kk * AFD_STRIDE + a] = splat2(v);
        }
        __syncthreads();

        #pragma unroll 8
        for (int kk = 0; kk < 32; kk++) {
            unsigned long long w = lds_b64(atw + (kk * ATOM_F + 2 * tx_j) * 4);
            uint32_t ab = aaf + (uint32_t)(kk * AFD_STRIDE + ag * 8) * 8;
            unsigned long long af0, af1, af2, af3, af4, af5, af6, af7;
            lds_v2u64(ab,      af0, af1);
            lds_v2u64(ab + 16, af2, af3);
            lds_v2u64(ab + 32, af4, af5);
            lds_v2u64(ab + 48, af6, af7);
            fma2(acc[0], af0, w); fma2(acc[1], af1, w);
            fma2(acc[2], af2, w); fma2(acc[3], af3, w);
            fma2(acc[4], af4, w); fma2(acc[5], af5, w);
            fma2(acc[6], af6, w); fma2(acc[7], af7, w);
        }
    }

    #pragma unroll
    for (int a = 0; a < 8; a++) {
        int atom = base + ag * 8 + a;
        if (atom < N_ATOMS) {
            float c = g_C[atom];
            float scale = g_S[atom] * INV_SQRT_F / fmaxf(c, 1.0f);
            float lo = __uint_as_float((uint32_t)(acc[a] & 0xffffffffULL));
            float hi = __uint_as_float((uint32_t)(acc[a] >> 32));
            *(float2*)(out + (size_t)atom * ATOM_F + 2 * tx_j) =
                make_float2(lo * scale, hi * scale);
        }
    }
}

// ---------------------------------------------------------------------------
// Launch
// ---------------------------------------------------------------------------
extern "C" void kernel_launch(void* const* d_in, const int* in_sizes, int n_in,
                              void* d_out, int out_size)
{
    const float* atom_fea = (const float*)d_in[0];
    const float* nbr_fea  = (const float*)d_in[1];
    const int*   nbr_idx  = (const int*)d_in[2];
    const float* w1       = (const float*)d_in[3];
    const float* b1       = (const float*)d_in[4];
    const float* w2       = (const float*)d_in[5];
    const float* b2       = (const float*)d_in[6];
    const float* tp_w     = (const float*)d_in[7];
    float*       out      = (float*)d_out;

    cudaFuncSetAttribute(edge_kernel,
                         cudaFuncAttributeMaxDynamicSharedMemorySize,
                         EDGE_SMEM_BYTES);

    zero_kernel<<<(N_ATOMS + 255) / 256, 256>>>();
    edge_kernel<<<N_CTAS, 256, EDGE_SMEM_BYTES>>>(nbr_fea, nbr_idx, w1, b1, w2, b2);
    out_kernel<<<(N_ATOMS + 31) / 32, 256>>>(atom_fea, tp_w, out);
}

// round 10
// speedup vs baseline: 2.3150x; 1.0992x over previous
#include <cuda_runtime.h>
#include <cuda_bf16.h>
#include <cstdint>

#define N_ATOMS 50000
#define M_NBR   32
#define NE      (N_ATOMS * M_NBR)   // 1,600,000 edges
#define NBR_F   64
#define ATOM_F  128
#define SH_DIM  9
#define INV_SQRT_F 0.08838834764831845f

#define TILE_E        128            // edges per tile (8 warps x 16 edges)
#define TILES_PER_CTA 4
#define N_CTAS (NE / (TILE_E * TILES_PER_CTA))   // 3125

// ---- edge-kernel smem layout (byte offsets from 1024-aligned base) ----
#define OFF_A_HI   0                 // 128 x 64 bf16, swizzled 128B rows (16384)
#define OFF_A_LO   16384             // 16384
#define OFF_B_HI   32768             // 64 x 64 bf16 row-major [k][j], swz (8192)
#define OFF_B_LO   40960             // 8192
#define OFF_BW     49152             // 32 x float4 {b1[2j],b1[2j+1],w2[2j],w2[2j+1]}
#define EDGE_SMEM_USED 49664
#define EDGE_SMEM_BYTES (EDGE_SMEM_USED + 1024)

__device__ float g_S[N_ATOMS];
__device__ float g_C[N_ATOMS];

__global__ void zero_kernel() {
    int i = blockIdx.x * blockDim.x + threadIdx.x;
    if (i < N_ATOMS) { g_S[i] = 0.0f; g_C[i] = 0.0f; }
}

// ======================= helpers =======================
__device__ __forceinline__ uint32_t smem_u32(const void* p) {
    uint32_t a;
    asm("{ .reg .u64 t; cvta.to.shared.u64 t, %1; cvt.u32.u64 %0, t; }"
        : "=r"(a) : "l"(p));
    return a;
}
__device__ __forceinline__ void sts64(uint32_t addr, unsigned long long v) {
    asm volatile("st.shared.b64 [%0], %1;" :: "r"(addr), "l"(v) : "memory");
}
__device__ __forceinline__ void sts16(uint32_t addr, unsigned short v) {
    asm volatile("st.shared.b16 [%0], %1;" :: "r"(addr), "h"(v) : "memory");
}
#define SMEM_SWZ(off) ((off) ^ (((off) >> 3) & 0x70))

__device__ __forceinline__ void ldsm_x4(uint32_t addr, uint32_t* r) {
    asm volatile("ldmatrix.sync.aligned.m8n8.x4.shared.b16 {%0,%1,%2,%3}, [%4];"
        : "=r"(r[0]), "=r"(r[1]), "=r"(r[2]), "=r"(r[3]) : "r"(addr));
}
__device__ __forceinline__ void ldsm_x2t(uint32_t addr, uint32_t& a, uint32_t& b) {
    asm volatile("ldmatrix.sync.aligned.m8n8.x2.trans.shared.b16 {%0,%1}, [%2];"
        : "=r"(a), "=r"(b) : "r"(addr));
}
__device__ __forceinline__ void mma_bf16(float* d, const uint32_t* a,
                                         uint32_t b0, uint32_t b1) {
    asm volatile("mma.sync.aligned.m16n8k16.row.col.f32.bf16.bf16.f32 "
        "{%0,%1,%2,%3}, {%4,%5,%6,%7}, {%8,%9}, {%0,%1,%2,%3};"
        : "+f"(d[0]), "+f"(d[1]), "+f"(d[2]), "+f"(d[3])
        : "r"(a[0]), "r"(a[1]), "r"(a[2]), "r"(a[3]), "r"(b0), "r"(b1));
}
__device__ __forceinline__ unsigned short bf_bits(__nv_bfloat16 b) {
    return *reinterpret_cast<unsigned short*>(&b);
}
__device__ __forceinline__ uint32_t cvt_bf2(float hi, float lo) {
    uint32_t r;
    asm("cvt.rn.bf16x2.f32 %0, %1, %2;" : "=r"(r) : "f"(hi), "f"(lo));
    return r;
}
__device__ __forceinline__ unsigned long long pack64(uint32_t lo, uint32_t hi) {
    unsigned long long v;
    asm("mov.b64 %0, {%1, %2};" : "=l"(v) : "r"(lo), "r"(hi));
    return v;
}

// ---------------------------------------------------------------------------
// Edge kernel: per 128-edge tile, h = radial @ w1 on HMMA (3-term bf16 hi/lo
// split, fp32 acc), epilogue softplus . w2[:,0] + atomics.
// B_hi fragments shared between A_hi and A_lo passes (LDSM 108->76/warp-tile).
// Next tile's A prefetched to L2 during the epilogue.
// ---------------------------------------------------------------------------
__global__ __launch_bounds__(256, 3) void edge_kernel(
    const float* __restrict__ nbr_fea,
    const int*   __restrict__ nbr_idx,
    const float* __restrict__ w1,
    const float* __restrict__ b1,
    const float* __restrict__ w2,
    const float* __restrict__ b2)
{
    extern __shared__ char dyn[];
    const uint32_t raw  = smem_u32(dyn);
    const uint32_t base = (raw + 1023u) & ~1023u;
    char* bp = dyn + (base - raw);

    const int tid  = threadIdx.x;
    const int wid  = tid >> 5;
    const int lane = tid & 31;
    const int gid  = lane >> 2;     // row group 0-7
    const int tid4 = lane & 3;      // col group 0-3

    // ---- stage B = w1 row-major [k][j], bf16 hi/lo, swizzled (once/CTA) ----
    #pragma unroll
    for (int it = 0; it < 16; it++) {
        int idx = it * 256 + tid;          // [0, 4096)
        int k = idx >> 6, j = idx & 63;
        float v = w1[idx];
        __nv_bfloat16 bh = __float2bfloat16(v);
        __nv_bfloat16 bl = __float2bfloat16(v - __bfloat162float(bh));
        uint32_t off = SMEM_SWZ((uint32_t)(k * 128 + j * 2));
        sts16(base + OFF_B_HI + off, bf_bits(bh));
        sts16(base + OFF_B_LO + off, bf_bits(bl));
    }
    if (tid < 32) {   // interleaved {b1[2t],b1[2t+1],w2[2t],w2[2t+1]}
        float4 bw;
        bw.x = b1[2 * tid];
        bw.y = b1[2 * tid + 1];
        bw.z = w2[(2 * tid) * SH_DIM];
        bw.w = w2[(2 * tid + 1) * SH_DIM];
        *(float4*)(bp + OFF_BW + tid * 16) = bw;
    }
    const float b2v = b2[0];

    // L2-prefetch first tile
    {
        const char* p = (const char*)(nbr_fea
                        + (size_t)(blockIdx.x * TILES_PER_CTA) * TILE_E * NBR_F);
        asm volatile("prefetch.global.L2 [%0];" :: "l"(p + tid * 128));
    }

    for (int t = 0; t < TILES_PER_CTA; t++) {
        const int tb = (blockIdx.x * TILES_PER_CTA + t) * TILE_E;

        // hoist idx loads for this tile (consumed at epilogue end)
        int ia0 = 0, ia1 = 0;
        if (tid4 == 0) {
            int r0 = wid * 16 + gid;
            ia0 = nbr_idx[tb + r0];
            ia1 = nbr_idx[tb + r0 + 8];
        }

        __syncthreads();   // prev tile's ldsm reads done / B ready (t==0)

        // ---- stage A = radial tile (128 x 64) bf16 hi/lo, packed cvt ----
        #pragma unroll
        for (int it = 0; it < 8; it++) {
            int idx = it * 256 + tid;      // [0, 2048) float4 quads
            int row = idx >> 4, q = idx & 15;
            float4 v = *(const float4*)(nbr_fea + (size_t)(tb + row) * NBR_F + q * 4);
            uint32_t h01 = cvt_bf2(v.y, v.x);
            uint32_t h23 = cvt_bf2(v.w, v.z);
            float f0 = __uint_as_float(h01 << 16);
            float f1 = __uint_as_float(h01 & 0xffff0000u);
            float f2 = __uint_as_float(h23 << 16);
            float f3 = __uint_as_float(h23 & 0xffff0000u);
            uint32_t l01 = cvt_bf2(v.y - f1, v.x - f0);
            uint32_t l23 = cvt_bf2(v.w - f3, v.z - f2);
            uint32_t off = SMEM_SWZ((uint32_t)(row * 128 + q * 8));
            sts64(base + OFF_A_HI + off, pack64(h01, h23));
            sts64(base + OFF_A_LO + off, pack64(l01, l23));
        }
        __syncthreads();

        // ---- mainloop ----
        float acc[8][4];
        #pragma unroll
        for (int nt = 0; nt < 8; nt++)
            #pragma unroll
            for (int c = 0; c < 4; c++) acc[nt][c] = 0.0f;

        // Pass 1: (A_hi + A_lo) . B_hi  — B fragment loaded once, used twice
        #pragma unroll
        for (int ks = 0; ks < 4; ks++) {
            uint32_t ah[4], al[4];
            uint32_t aoff = (uint32_t)((wid * 16 + (lane & 15)) * 128
                                       + ks * 32 + (lane >> 4) * 16);
            ldsm_x4(base + OFF_A_HI + SMEM_SWZ(aoff), ah);
            ldsm_x4(base + OFF_A_LO + SMEM_SWZ(aoff), al);
            #pragma unroll
            for (int nt = 0; nt < 8; nt++) {
                uint32_t boff = (uint32_t)((ks * 16 + (lane & 15)) * 128 + nt * 16);
                uint32_t b0, b1r;
                ldsm_x2t(base + OFF_B_HI + SMEM_SWZ(boff), b0, b1r);
                mma_bf16(acc[nt], ah, b0, b1r);
                mma_bf16(acc[nt], al, b0, b1r);
            }
        }
        // Pass 2: A_hi . B_lo
        #pragma unroll
        for (int ks = 0; ks < 4; ks++) {
            uint32_t ah[4];
            uint32_t aoff = (uint32_t)((wid * 16 + (lane & 15)) * 128
                                       + ks * 32 + (lane >> 4) * 16);
            ldsm_x4(base + OFF_A_HI + SMEM_SWZ(aoff), ah);
            #pragma unroll
            for (int nt = 0; nt < 8; nt++) {
                uint32_t boff = (uint32_t)((ks * 16 + (lane & 15)) * 128 + nt * 16);
                uint32_t b0, b1r;
                ldsm_x2t(base + OFF_B_LO + SMEM_SWZ(boff), b0, b1r);
                mma_bf16(acc[nt], ah, b0, b1r);
            }
        }

        // L2-prefetch next tile's A while epilogue runs
        if (t + 1 < TILES_PER_CTA) {
            const char* p = (const char*)(nbr_fea + (size_t)(tb + TILE_E) * NBR_F);
            asm volatile("prefetch.global.L2 [%0];" :: "l"(p + tid * 128));
        }

        // ---- epilogue: softplus . w2, quad-reduce, atomics ----
        float s0 = 0.0f, s1 = 0.0f;
        #pragma unroll
        for (int nt = 0; nt < 8; nt++) {
            int colp = nt * 4 + tid4;     // float4 index = col/2
            float4 bw = *(const float4*)(bp + OFF_BW + colp * 16);
            float h0 = acc[nt][0] + bw.x;   // row gid
            float h1 = acc[nt][1] + bw.y;
            float h2 = acc[nt][2] + bw.x;   // row gid+8
            float h3 = acc[nt][3] + bw.y;
            float p0 = fmaxf(h0, 0.0f) + __logf(1.0f + __expf(-fabsf(h0)));
            float p1 = fmaxf(h1, 0.0f) + __logf(1.0f + __expf(-fabsf(h1)));
            float p2 = fmaxf(h2, 0.0f) + __logf(1.0f + __expf(-fabsf(h2)));
            float p3 = fmaxf(h3, 0.0f) + __logf(1.0f + __expf(-fabsf(h3)));
            s0 = fmaf(p0, bw.z, s0); s0 = fmaf(p1, bw.w, s0);
            s1 = fmaf(p2, bw.z, s1); s1 = fmaf(p3, bw.w, s1);
        }
        s0 += __shfl_xor_sync(0xffffffffu, s0, 1);
        s0 += __shfl_xor_sync(0xffffffffu, s0, 2);
        s1 += __shfl_xor_sync(0xffffffffu, s1, 1);
        s1 += __shfl_xor_sync(0xffffffffu, s1, 2);
        if (tid4 == 0) {
            int a0 = ia0;
            a0 = (a0 < 0) ? 0 : (a0 >= N_ATOMS ? N_ATOMS - 1 : a0);
            atomicAdd(&g_S[a0], s0 + b2v);
            atomicAdd(&g_C[a0], 1.0f);
            int a1 = ia1;
            a1 = (a1 < 0) ? 0 : (a1 >= N_ATOMS ? N_ATOMS - 1 : a1);
            atomicAdd(&g_S[a1], s1 + b2v);
            atomicAdd(&g_C[a1], 1.0f);
        }
    }
}

// ---------------------------------------------------------------------------
// Output GEMM (f32x2): out[i,:] = (atom_fea[i,:] @ tp_w) * scale(i)
// ---------------------------------------------------------------------------
__device__ __forceinline__ unsigned long long lds_b64(uint32_t addr) {
    unsigned long long v;
    asm volatile("ld.shared.b64 %0, [%1];" : "=l"(v) : "r"(addr));
    return v;
}
__device__ __forceinline__ void lds_v2u64(uint32_t addr, unsigned long long& a,
                                          unsigned long long& b) {
    asm volatile("ld.shared.v2.u64 {%0, %1}, [%2];" : "=l"(a), "=l"(b) : "r"(addr));
}
__device__ __forceinline__ void fma2(unsigned long long& d, unsigned long long a,
                                     unsigned long long b) {
    asm("fma.rn.f32x2 %0, %1, %2, %0;" : "+l"(d) : "l"(a), "l"(b));
}
__device__ __forceinline__ unsigned long long splat2(float x) {
    unsigned long long v;
    asm("mov.b64 %0, {%1, %2};" : "=l"(v) : "f"(x), "f"(x));
    return v;
}

#define AFD_STRIDE 34

__global__ __launch_bounds__(256) void out_kernel(
    const float* __restrict__ atom_fea,
    const float* __restrict__ tp_w,
    float* __restrict__ out)
{
    __shared__ float s_tw[32 * ATOM_F];                     // 16 KB
    __shared__ unsigned long long s_afd[32 * AFD_STRIDE];   // 8.5 KB

    const int tid  = threadIdx.x;
    const int base = blockIdx.x * 32;
    const int tx_j = tid & 63;
    const int ag   = tid >> 6;

    const uint32_t atw = smem_u32(s_tw);
    const uint32_t aaf = smem_u32(s_afd);

    unsigned long long acc[8];
    #pragma unroll
    for (int a = 0; a < 8; a++) acc[a] = 0ULL;

    for (int kt = 0; kt < ATOM_F / 32; kt++) {
        __syncthreads();
        for (int i = tid; i < 32 * ATOM_F; i += 256)
            s_tw[i] = tp_w[(size_t)(kt * 32) * ATOM_F + i];
        for (int i = tid; i < 32 * 32; i += 256) {
            int a = i >> 5, kk = i & 31;
            int atom = base + a;
            float v = (atom < N_ATOMS)
                        ? atom_fea[(size_t)atom * ATOM_F + kt * 32 + kk]
                        : 0.0f;
            s_afd[kk * AFD_STRIDE + a] = splat2(v);
        }
        __syncthreads();

        #pragma unroll 8
        for (int kk = 0; kk < 32; kk++) {
            unsigned long long w = lds_b64(atw + (kk * ATOM_F + 2 * tx_j) * 4);
            uint32_t ab = aaf + (uint32_t)(kk * AFD_STRIDE + ag * 8) * 8;
            unsigned long long af0, af1, af2, af3, af4, af5, af6, af7;
            lds_v2u64(ab,      af0, af1);
            lds_v2u64(ab + 16, af2, af3);
            lds_v2u64(ab + 32, af4, af5);
            lds_v2u64(ab + 48, af6, af7);
            fma2(acc[0], af0, w); fma2(acc[1], af1, w);
            fma2(acc[2], af2, w); fma2(acc[3], af3, w);
            fma2(acc[4], af4, w); fma2(acc[5], af5, w);
            fma2(acc[6], af6, w); fma2(acc[7], af7, w);
        }
    }

    #pragma unroll
    for (int a = 0; a < 8; a++) {
        int atom = base + ag * 8 + a;
        if (atom < N_ATOMS) {
            float c = g_C[atom];
            float scale = g_S[atom] * INV_SQRT_F / fmaxf(c, 1.0f);
            float lo = __uint_as_float((uint32_t)(acc[a] & 0xffffffffULL));
            float hi = __uint_as_float((uint32_t)(acc[a] >> 32));
            *(float2*)(out + (size_t)atom * ATOM_F + 2 * tx_j) =
                make_float2(lo * scale, hi * scale);
        }
    }
}

// ---------------------------------------------------------------------------
// Launch
// ---------------------------------------------------------------------------
extern "C" void kernel_launch(void* const* d_in, const int* in_sizes, int n_in,
                              void* d_out, int out_size)
{
    const float* atom_fea = (const float*)d_in[0];
    const float* nbr_fea  = (const float*)d_in[1];
    const int*   nbr_idx  = (const int*)d_in[2];
    const float* w1       = (const float*)d_in[3];
    const float* b1       = (const float*)d_in[4];
    const float* w2       = (const float*)d_in[5];
    const float* b2       = (const float*)d_in[6];
    const float* tp_w     = (const float*)d_in[7];
    float*       out      = (float*)d_out;

    cudaFuncSetAttribute(edge_kernel,
                         cudaFuncAttributeMaxDynamicSharedMemorySize,
                         EDGE_SMEM_BYTES);

    zero_kernel<<<(N_ATOMS + 255) / 256, 256>>>();
    edge_kernel<<<N_CTAS, 256, EDGE_SMEM_BYTES>>>(nbr_fea, nbr_idx, w1, b1, w2, b2);
    out_kernel<<<(N_ATOMS + 31) / 32, 256>>>(atom_fea, tp_w, out);
}

// round 11
// speedup vs baseline: 3.5355x; 1.5272x over previous
#include <cuda_runtime.h>
#include <cuda_bf16.h>
#include <cstdint>

#define N_ATOMS 50000
#define M_NBR   32
#define NE      (N_ATOMS * M_NBR)   // 1,600,000 edges
#define NBR_F   64
#define ATOM_F  128
#define SH_DIM  9
#define INV_SQRT_F 0.08838834764831845f

#define TILE_E        128            // edges per tile (8 warps x 16 edges)
#define TILES_PER_CTA 8
#define N_CTAS (NE / (TILE_E * TILES_PER_CTA))   // 1563 is wrong; NE/(1024)=1562.5 -> use 1563 w/ guard? NE=1600000, 1600000/1024 = 1562.5
// NE = 1,600,000 = 1024 * 1562.5 -> not divisible. Use 12500 tiles total, 8 per CTA
#define N_TILES_TOTAL (NE / TILE_E)              // 12500
#define N_EDGE_CTAS   ((N_TILES_TOTAL + TILES_PER_CTA - 1) / TILES_PER_CTA)  // 1563

// ---- edge-kernel smem layout (byte offsets from 1024-aligned base) ----
#define OFF_A_HI   0                 // 128 x 64 bf16, swizzled 128B rows (16384)
#define OFF_A_LO   16384             // 16384
#define OFF_B_HI   32768             // 64 x 64 bf16 row-major [k][j], swz (8192)
#define OFF_B_LO   40960             // 8192
#define OFF_BW     49152             // 32 x float4 {b1[2j],b1[2j+1],w2[2j],w2[2j+1]}
#define OFF_RAW    49664             // 128 x 64 f32 raw tile (32768)
#define EDGE_SMEM_USED 82432
#define EDGE_SMEM_BYTES (EDGE_SMEM_USED + 1024)

__device__ float g_S[N_ATOMS];
__device__ float g_C[N_ATOMS];

__global__ void zero_kernel() {
    int i = blockIdx.x * blockDim.x + threadIdx.x;
    if (i < N_ATOMS) { g_S[i] = 0.0f; g_C[i] = 0.0f; }
}

// ======================= helpers =======================
__device__ __forceinline__ uint32_t smem_u32(const void* p) {
    uint32_t a;
    asm("{ .reg .u64 t; cvta.to.shared.u64 t, %1; cvt.u32.u64 %0, t; }"
        : "=r"(a) : "l"(p));
    return a;
}
__device__ __forceinline__ void sts64(uint32_t addr, unsigned long long v) {
    asm volatile("st.shared.b64 [%0], %1;" :: "r"(addr), "l"(v) : "memory");
}
__device__ __forceinline__ void sts16(uint32_t addr, unsigned short v) {
    asm volatile("st.shared.b16 [%0], %1;" :: "r"(addr), "h"(v) : "memory");
}
#define SMEM_SWZ(off) ((off) ^ (((off) >> 3) & 0x70))

__device__ __forceinline__ void ldsm_x4(uint32_t addr, uint32_t* r) {
    asm volatile("ldmatrix.sync.aligned.m8n8.x4.shared.b16 {%0,%1,%2,%3}, [%4];"
        : "=r"(r[0]), "=r"(r[1]), "=r"(r[2]), "=r"(r[3]) : "r"(addr));
}
__device__ __forceinline__ void ldsm_x2t(uint32_t addr, uint32_t& a, uint32_t& b) {
    asm volatile("ldmatrix.sync.aligned.m8n8.x2.trans.shared.b16 {%0,%1}, [%2];"
        : "=r"(a), "=r"(b) : "r"(addr));
}
__device__ __forceinline__ void mma_bf16(float* d, const uint32_t* a,
                                         uint32_t b0, uint32_t b1) {
    asm volatile("mma.sync.aligned.m16n8k16.row.col.f32.bf16.bf16.f32 "
        "{%0,%1,%2,%3}, {%4,%5,%6,%7}, {%8,%9}, {%0,%1,%2,%3};"
        : "+f"(d[0]), "+f"(d[1]), "+f"(d[2]), "+f"(d[3])
        : "r"(a[0]), "r"(a[1]), "r"(a[2]), "r"(a[3]), "r"(b0), "r"(b1));
}
__device__ __forceinline__ unsigned short bf_bits(__nv_bfloat16 b) {
    return *reinterpret_cast<unsigned short*>(&b);
}
__device__ __forceinline__ uint32_t cvt_bf2(float hi, float lo) {
    uint32_t r;
    asm("cvt.rn.bf16x2.f32 %0, %1, %2;" : "=r"(r) : "f"(hi), "f"(lo));
    return r;
}
__device__ __forceinline__ unsigned long long pack64(uint32_t lo, uint32_t hi) {
    unsigned long long v;
    asm("mov.b64 %0, {%1, %2};" : "=l"(v) : "r"(lo), "r"(hi));
    return v;
}
__device__ __forceinline__ void cpasync16(uint32_t dst, const void* src) {
    asm volatile("cp.async.ca.shared.global [%0], [%1], 16;"
        :: "r"(dst), "l"(src) : "memory");
}
__device__ __forceinline__ void cpasync_commit() {
    asm volatile("cp.async.commit_group;" ::: "memory");
}
__device__ __forceinline__ void cpasync_wait0() {
    asm volatile("cp.async.wait_group 0;" ::: "memory");
}

// ---------------------------------------------------------------------------
// Edge kernel: per 128-edge tile, h = radial @ w1 on HMMA (3-term bf16 hi/lo
// split, fp32 acc), epilogue softplus . w2[:,0] + atomics.
// Raw fp32 tiles double-buffered via cp.async: tile t+1 streams into smem
// during tile t's mainloop/epilogue; conversion reads smem, not global.
// ---------------------------------------------------------------------------
__global__ __launch_bounds__(256, 2) void edge_kernel(
    const float* __restrict__ nbr_fea,
    const int*   __restrict__ nbr_idx,
    const float* __restrict__ w1,
    const float* __restrict__ b1,
    const float* __restrict__ w2,
    const float* __restrict__ b2)
{
    extern __shared__ char dyn[];
    const uint32_t raw_a = smem_u32(dyn);
    const uint32_t base  = (raw_a + 1023u) & ~1023u;
    char* bp = dyn + (base - raw_a);

    const int tid  = threadIdx.x;
    const int wid  = tid >> 5;
    const int lane = tid & 31;
    const int gid  = lane >> 2;     // row group 0-7
    const int tid4 = lane & 3;      // col group 0-3

    const int tile0   = blockIdx.x * TILES_PER_CTA;
    const int n_tiles = (tile0 + TILES_PER_CTA <= N_TILES_TOTAL)
                        ? TILES_PER_CTA : (N_TILES_TOTAL - tile0);
    if (n_tiles <= 0) return;

    // ---- stage B = w1 row-major [k][j], bf16 hi/lo, swizzled (once/CTA) ----
    #pragma unroll
    for (int it = 0; it < 16; it++) {
        int idx = it * 256 + tid;          // [0, 4096)
        int k = idx >> 6, j = idx & 63;
        float v = w1[idx];
        __nv_bfloat16 bh = __float2bfloat16(v);
        __nv_bfloat16 bl = __float2bfloat16(v - __bfloat162float(bh));
        uint32_t off = SMEM_SWZ((uint32_t)(k * 128 + j * 2));
        sts16(base + OFF_B_HI + off, bf_bits(bh));
        sts16(base + OFF_B_LO + off, bf_bits(bl));
    }
    if (tid < 32) {   // interleaved {b1[2t],b1[2t+1],w2[2t],w2[2t+1]}
        float4 bw;
        bw.x = b1[2 * tid];
        bw.y = b1[2 * tid + 1];
        bw.z = w2[(2 * tid) * SH_DIM];
        bw.w = w2[(2 * tid + 1) * SH_DIM];
        *(float4*)(bp + OFF_BW + tid * 16) = bw;
    }
    const float b2v = b2[0];

    // ---- async-prefetch tile 0 raw fp32 ----
    {
        const float* src = nbr_fea + (size_t)tile0 * TILE_E * NBR_F;
        #pragma unroll
        for (int it = 0; it < 8; it++) {
            int idx = it * 256 + tid;
            cpasync16(base + OFF_RAW + idx * 16, src + idx * 4);
        }
        cpasync_commit();
    }

    for (int t = 0; t < n_tiles; t++) {
        const int tb = (tile0 + t) * TILE_E;

        // hoist idx loads for this tile (consumed at epilogue end)
        int ia0 = 0, ia1 = 0;
        if (tid4 == 0) {
            int r0 = wid * 16 + gid;
            ia0 = nbr_idx[tb + r0];
            ia1 = nbr_idx[tb + r0 + 8];
        }

        cpasync_wait0();
        __syncthreads();   // raw tile ready; prev tile's ldsm reads done

        // ---- convert raw (smem) -> A bf16 hi/lo planes ----
        #pragma unroll
        for (int it = 0; it < 8; it++) {
            int idx = it * 256 + tid;      // [0, 2048) float4 quads
            int row = idx >> 4, q = idx & 15;
            float4 v = *(const float4*)(bp + OFF_RAW + idx * 16);
            uint32_t h01 = cvt_bf2(v.y, v.x);
            uint32_t h23 = cvt_bf2(v.w, v.z);
            float f0 = __uint_as_float(h01 << 16);
            float f1 = __uint_as_float(h01 & 0xffff0000u);
            float f2 = __uint_as_float(h23 << 16);
            float f3 = __uint_as_float(h23 & 0xffff0000u);
            uint32_t l01 = cvt_bf2(v.y - f1, v.x - f0);
            uint32_t l23 = cvt_bf2(v.w - f3, v.z - f2);
            uint32_t off = SMEM_SWZ((uint32_t)(row * 128 + q * 8));
            sts64(base + OFF_A_HI + off, pack64(h01, h23));
            sts64(base + OFF_A_LO + off, pack64(l01, l23));
        }
        __syncthreads();   // A ready; raw buffer free for refill

        // ---- kick off next tile's raw prefetch (overlaps mainloop) ----
        if (t + 1 < n_tiles) {
            const float* src = nbr_fea + (size_t)(tb + TILE_E) * NBR_F;
            #pragma unroll
            for (int it = 0; it < 8; it++) {
                int idx = it * 256 + tid;
                cpasync16(base + OFF_RAW + idx * 16, src + idx * 4);
            }
            cpasync_commit();
        }

        // ---- mainloop ----
        float acc[8][4];
        #pragma unroll
        for (int nt = 0; nt < 8; nt++)
            #pragma unroll
            for (int c = 0; c < 4; c++) acc[nt][c] = 0.0f;

        // Pass 1: (A_hi + A_lo) . B_hi  — B fragment loaded once, used twice
        #pragma unroll
        for (int ks = 0; ks < 4; ks++) {
            uint32_t ah[4], al[4];
            uint32_t aoff = (uint32_t)((wid * 16 + (lane & 15)) * 128
                                       + ks * 32 + (lane >> 4) * 16);
            ldsm_x4(base + OFF_A_HI + SMEM_SWZ(aoff), ah);
            ldsm_x4(base + OFF_A_LO + SMEM_SWZ(aoff), al);
            #pragma unroll
            for (int nt = 0; nt < 8; nt++) {
                uint32_t boff = (uint32_t)((ks * 16 + (lane & 15)) * 128 + nt * 16);
                uint32_t b0, b1r;
                ldsm_x2t(base + OFF_B_HI + SMEM_SWZ(boff), b0, b1r);
                mma_bf16(acc[nt], ah, b0, b1r);
                mma_bf16(acc[nt], al, b0, b1r);
            }
        }
        // Pass 2: A_hi . B_lo
        #pragma unroll
        for (int ks = 0; ks < 4; ks++) {
            uint32_t ah[4];
            uint32_t aoff = (uint32_t)((wid * 16 + (lane & 15)) * 128
                                       + ks * 32 + (lane >> 4) * 16);
            ldsm_x4(base + OFF_A_HI + SMEM_SWZ(aoff), ah);
            #pragma unroll
            for (int nt = 0; nt < 8; nt++) {
                uint32_t boff = (uint32_t)((ks * 16 + (lane & 15)) * 128 + nt * 16);
                uint32_t b0, b1r;
                ldsm_x2t(base + OFF_B_LO + SMEM_SWZ(boff), b0, b1r);
                mma_bf16(acc[nt], ah, b0, b1r);
            }
        }

        // ---- epilogue: softplus . w2, quad-reduce, atomics ----
        float s0 = 0.0f, s1 = 0.0f;
        #pragma unroll
        for (int nt = 0; nt < 8; nt++) {
            int colp = nt * 4 + tid4;     // float4 index = col/2
            float4 bw = *(const float4*)(bp + OFF_BW + colp * 16);
            float h0 = acc[nt][0] + bw.x;   // row gid
            float h1 = acc[nt][1] + bw.y;
            float h2 = acc[nt][2] + bw.x;   // row gid+8
            float h3 = acc[nt][3] + bw.y;
            float p0 = fmaxf(h0, 0.0f) + __logf(1.0f + __expf(-fabsf(h0)));
            float p1 = fmaxf(h1, 0.0f) + __logf(1.0f + __expf(-fabsf(h1)));
            float p2 = fmaxf(h2, 0.0f) + __logf(1.0f + __expf(-fabsf(h2)));
            float p3 = fmaxf(h3, 0.0f) + __logf(1.0f + __expf(-fabsf(h3)));
            s0 = fmaf(p0, bw.z, s0); s0 = fmaf(p1, bw.w, s0);
            s1 = fmaf(p2, bw.z, s1); s1 = fmaf(p3, bw.w, s1);
        }
        s0 += __shfl_xor_sync(0xffffffffu, s0, 1);
        s0 += __shfl_xor_sync(0xffffffffu, s0, 2);
        s1 += __shfl_xor_sync(0xffffffffu, s1, 1);
        s1 += __shfl_xor_sync(0xffffffffu, s1, 2);
        if (tid4 == 0) {
            int a0 = ia0;
            a0 = (a0 < 0) ? 0 : (a0 >= N_ATOMS ? N_ATOMS - 1 : a0);
            atomicAdd(&g_S[a0], s0 + b2v);
            atomicAdd(&g_C[a0], 1.0f);
            int a1 = ia1;
            a1 = (a1 < 0) ? 0 : (a1 >= N_ATOMS ? N_ATOMS - 1 : a1);
            atomicAdd(&g_S[a1], s1 + b2v);
            atomicAdd(&g_C[a1], 1.0f);
        }
    }
}

// ---------------------------------------------------------------------------
// Output GEMM on HMMA: out[i,:] = (atom_fea[i,:] @ tp_w) * scale(i)
// CTA tile: 64 atoms x 128 cols, K=128 split into 2 k-chunks of 64 (so all
// smem planes keep the proven 128-byte-row swizzled layout from edge_kernel).
// Warp w: m-tile mt=w&3 (16 atoms), col-half ch=w>>2 (64 cols). 3-pass bf16.
// ---------------------------------------------------------------------------
#define OT_M 64
#define N_OUT_CTAS ((N_ATOMS + OT_M - 1) / OT_M)   // 782

#define O_A_HI 0        // 2 kc-planes x 8192 (64 rows x 128B)
#define O_A_LO 16384
#define O_B_HI 32768    // 4 planes [kc][ch] x 8192
#define O_B_LO 65536
#define OUT_SMEM_USED 98304
#define OUT_SMEM_BYTES (OUT_SMEM_USED + 1024)

__global__ __launch_bounds__(256, 2) void out_kernel(
    const float* __restrict__ atom_fea,
    const float* __restrict__ tp_w,
    float* __restrict__ out)
{
    extern __shared__ char dyn[];
    const uint32_t raw_a = smem_u32(dyn);
    const uint32_t base  = (raw_a + 1023u) & ~1023u;

    const int tid  = threadIdx.x;
    const int wid  = tid >> 5;
    const int lane = tid & 31;
    const int gid  = lane >> 2;
    const int tid4 = lane & 3;
    const int mt   = wid & 3;       // m-tile (16 atoms)
    const int ch   = wid >> 2;      // col half (64 cols)
    const int abase = blockIdx.x * OT_M;

    // ---- stage B = tp_w [k][j] bf16 hi/lo into 4 planes [kc][jh] ----
    #pragma unroll
    for (int it = 0; it < 64; it++) {
        int idx = it * 256 + tid;          // [0, 16384)
        int k = idx >> 7, j = idx & 127;
        float v = tp_w[idx];
        __nv_bfloat16 bh = __float2bfloat16(v);
        __nv_bfloat16 bl = __float2bfloat16(v - __bfloat162float(bh));
        uint32_t plane = (uint32_t)(((k >> 6) * 2 + (j >> 6)) * 8192);
        uint32_t off = plane + SMEM_SWZ((uint32_t)((k & 63) * 128 + (j & 63) * 2));
        sts16(base + O_B_HI + off, bf_bits(bh));
        sts16(base + O_B_LO + off, bf_bits(bl));
    }

    // ---- stage A = atom_fea tile (64 atoms x 128 k) bf16 hi/lo, 2 kc planes ----
    #pragma unroll
    for (int it = 0; it < 8; it++) {
        int idx = it * 256 + tid;          // [0, 2048) float4 quads
        int row = idx >> 5, q = idx & 31;
        int kc = q >> 4, qq = q & 15;
        int atom = abase + row;
        float4 v = make_float4(0.f, 0.f, 0.f, 0.f);
        if (atom < N_ATOMS)
            v = *(const float4*)(atom_fea + (size_t)atom * ATOM_F + q * 4);
        uint32_t h01 = cvt_bf2(v.y, v.x);
        uint32_t h23 = cvt_bf2(v.w, v.z);
        float f0 = __uint_as_float(h01 << 16);
        float f1 = __uint_as_float(h01 & 0xffff0000u);
        float f2 = __uint_as_float(h23 << 16);
        float f3 = __uint_as_float(h23 & 0xffff0000u);
        uint32_t l01 = cvt_bf2(v.y - f1, v.x - f0);
        uint32_t l23 = cvt_bf2(v.w - f3, v.z - f2);
        uint32_t off = (uint32_t)(kc * 8192)
                     + SMEM_SWZ((uint32_t)(row * 128 + qq * 8));
        sts64(base + O_A_HI + off, pack64(h01, h23));
        sts64(base + O_A_LO + off, pack64(l01, l23));
    }
    __syncthreads();

    // ---- mainloop: 2 k-chunks x 4 ks, 3-pass hi/lo ----
    float acc[8][4];
    #pragma unroll
    for (int nt = 0; nt < 8; nt++)
        #pragma unroll
        for (int c = 0; c < 4; c++) acc[nt][c] = 0.0f;

    #pragma unroll
    for (int kc = 0; kc < 2; kc++) {
        const uint32_t apl = (uint32_t)(kc * 8192);
        const uint32_t bpl = (uint32_t)((kc * 2 + ch) * 8192);
        #pragma unroll
        for (int ks = 0; ks < 4; ks++) {
            uint32_t ah[4], al[4];
            uint32_t aoff = apl + SMEM_SWZ((uint32_t)((mt * 16 + (lane & 15)) * 128
                                           + ks * 32 + (lane >> 4) * 16));
            ldsm_x4(base + O_A_HI + aoff, ah);
            ldsm_x4(base + O_A_LO + aoff, al);
            #pragma unroll
            for (int nt = 0; nt < 8; nt++) {
                uint32_t boff = bpl + SMEM_SWZ((uint32_t)((ks * 16 + (lane & 15)) * 128
                                               + nt * 16));
                uint32_t b0, b1r;
                ldsm_x2t(base + O_B_HI + boff, b0, b1r);
                mma_bf16(acc[nt], ah, b0, b1r);
                mma_bf16(acc[nt], al, b0, b1r);
                ldsm_x2t(base + O_B_LO + boff, b0, b1r);
                mma_bf16(acc[nt], ah, b0, b1r);
            }
        }
    }

    // ---- epilogue: per-atom scale, write float2 pairs ----
    int atomA = abase + mt * 16 + gid;
    int atomB = atomA + 8;
    float scA = 0.0f, scB = 0.0f;
    if (atomA < N_ATOMS)
        scA = g_S[atomA] * INV_SQRT_F / fmaxf(g_C[atomA], 1.0f);
    if (atomB < N_ATOMS)
        scB = g_S[atomB] * INV_SQRT_F / fmaxf(g_C[atomB], 1.0f);

    #pragma unroll
    for (int nt = 0; nt < 8; nt++) {
        int col = ch * 64 + nt * 8 + tid4 * 2;
        if (atomA < N_ATOMS)
            *(float2*)(out + (size_t)atomA * ATOM_F + col) =
                make_float2(acc[nt][0] * scA, acc[nt][1] * scA);
        if (atomB < N_ATOMS)
            *(float2*)(out + (size_t)atomB * ATOM_F + col) =
                make_float2(acc[nt][2] * scB, acc[nt][3] * scB);
    }
}

// ---------------------------------------------------------------------------
// Launch
// ---------------------------------------------------------------------------
extern "C" void kernel_launch(void* const* d_in, const int* in_sizes, int n_in,
                              void* d_out, int out_size)
{
    const float* atom_fea = (const float*)d_in[0];
    const float* nbr_fea  = (const float*)d_in[1];
    const int*   nbr_idx  = (const int*)d_in[2];
    const float* w1       = (const float*)d_in[3];
    const float* b1       = (const float*)d_in[4];
    const float* w2       = (const float*)d_in[5];
    const float* b2       = (const float*)d_in[6];
    const float* tp_w     = (const float*)d_in[7];
    float*       out      = (float*)d_out;

    cudaFuncSetAttribute(edge_kernel,
                         cudaFuncAttributeMaxDynamicSharedMemorySize,
                         EDGE_SMEM_BYTES);
    cudaFuncSetAttribute(out_kernel,
                         cudaFuncAttributeMaxDynamicSharedMemorySize,
                         OUT_SMEM_BYTES);

    zero_kernel<<<(N_ATOMS + 255) / 256, 256>>>();
    edge_kernel<<<N_EDGE_CTAS, 256, EDGE_SMEM_BYTES>>>(nbr_fea, nbr_idx,
                                                       w1, b1, w2, b2);
    out_kernel<<<N_OUT_CTAS, 256, OUT_SMEM_BYTES>>>(atom_fea, tp_w, out);
}